// round 17
// baseline (speedup 1.0000x reference)
#include <cuda_runtime.h>
#include <cuda_fp16.h>
#include <cstdint>
#include <math.h>

#define LQ 8192
#define LK 8192
#define DIM 128
#define KCH 8
#define NCH 8   // qk n-chunks
#define SCALE 0.08838834764831845f  // 1/sqrt(128)

#define STRQ 136  // fp16 elems per smem row, 128-wide tiles (272B, conflict-free)
#define STRP 72   // fp16 elems per smem row, 64-wide tiles (144B)

// ---------------- device scratch ----------------
__device__ __half g_qh[(size_t)LQ * DIM];
__device__ __half g_kh[(size_t)LK * DIM];
__device__ __half g_vth[(size_t)DIM * LK];          // V^T [d][k]
__device__ __half g_ef16[(size_t)LQ * LK];          // unnormalized e, fp16
__device__ float g_lpart[(size_t)LQ * NCH];
__device__ float g_il[LQ];
__device__ float g_opart[(size_t)KCH * LQ * DIM];

// ---------------- helpers ----------------
__device__ __forceinline__ uint32_t smem_u32(const void* p) {
    uint32_t a;
    asm("{ .reg .u64 t; cvta.to.shared.u64 t, %1; cvt.u32.u64 %0, t; }" : "=r"(a) : "l"(p));
    return a;
}
__device__ __forceinline__ void ldsm4(uint32_t (&r)[4], uint32_t addr) {
    asm volatile("ldmatrix.sync.aligned.m8n8.x4.shared.b16 {%0,%1,%2,%3}, [%4];"
        : "=r"(r[0]), "=r"(r[1]), "=r"(r[2]), "=r"(r[3]) : "r"(addr));
}
__device__ __forceinline__ void mma16816(float (&c)[4], const uint32_t (&a)[4],
                                         uint32_t b0, uint32_t b1) {
    asm volatile("mma.sync.aligned.m16n8k16.row.col.f32.f16.f16.f32 "
        "{%0,%1,%2,%3}, {%4,%5,%6,%7}, {%8,%9}, {%0,%1,%2,%3};"
        : "+f"(c[0]), "+f"(c[1]), "+f"(c[2]), "+f"(c[3])
        : "r"(a[0]), "r"(a[1]), "r"(a[2]), "r"(a[3]), "r"(b0), "r"(b1));
}
__device__ __forceinline__ void cpasync16(uint32_t dst, const void* src) {
    asm volatile("cp.async.cg.shared.global [%0], [%1], 16;" :: "r"(dst), "l"(src));
}
#define CP_COMMIT() asm volatile("cp.async.commit_group;" ::: "memory")
#define CP_WAIT(N)  asm volatile("cp.async.wait_group %0;" :: "n"(N) : "memory")
__device__ __forceinline__ uint32_t h2u(__half2 h) { return *reinterpret_cast<uint32_t*>(&h); }

// ---------------------------------------------------------------------------
// prep: fp32 -> fp16 (Q prescaled, K, V transposed)
// ---------------------------------------------------------------------------
__global__ __launch_bounds__(256) void prep_kernel(const float* __restrict__ Q,
                                                   const float* __restrict__ K,
                                                   const float* __restrict__ V) {
    size_t i = (size_t)blockIdx.x * 256 + threadIdx.x;
    g_qh[i] = __float2half_rn(Q[i] * SCALE);
    g_kh[i] = __float2half_rn(K[i]);
    size_t kr = i >> 7, d = i & 127;
    g_vth[d * LK + kr] = __float2half_rn(V[i]);
}

// ---------------------------------------------------------------------------
// Kernel A (streaming): e = exp(Qs @ K^T) -> g_ef16 + row partial sums.
// Grid (NCH, LQ/128): CTA keeps Q [128] resident, streams 8 K tiles of 128
// through a double-buffered cp.async ring. Warp tile 32m x 64n.
// ---------------------------------------------------------------------------
__global__ __launch_bounds__(256, 2) void qk_hmma_kernel() {
    extern __shared__ __align__(16) char smem[];
    const uint32_t qb = smem_u32(smem);         // Q: [128][STRQ]
    const uint32_t kbb = qb + 128 * STRQ * 2;   // K: 2 x [128][STRQ]
    const int KBUF = 128 * STRQ * 2;

    const int tid = threadIdx.x, lane = tid & 31, wid = tid >> 5;
    const int m0 = blockIdx.y * 128;
    const int nbase = blockIdx.x * (LK / NCH);

    const int wm = (wid >> 1) * 32, wn = (wid & 1) * 64;
    const int arow = lane & 15, acol = (lane >> 4) * 8;
    const int r0 = lane >> 2, c0 = (lane & 3) * 2;

    // prologue: Q + K(0), one group
#pragma unroll
    for (int i = 0; i < 8; i++) {
        int idx = i * 256 + tid;
        int row = idx >> 4, seg = idx & 15;
        cpasync16(qb + row * 272 + seg * 16, g_qh + (size_t)(m0 + row) * DIM + seg * 8);
    }
#pragma unroll
    for (int i = 0; i < 8; i++) {
        int idx = i * 256 + tid;
        int row = idx >> 4, seg = idx & 15;
        cpasync16(kbb + row * 272 + seg * 16, g_kh + (size_t)(nbase + row) * DIM + seg * 8);
    }
    CP_COMMIT();

    float sacc[2][2] = {{0.f, 0.f}, {0.f, 0.f}};

    for (int t = 0; t < NCH; t++) {
        CP_WAIT(0);           // Q(once) + K(t) resident
        __syncthreads();      // all warps done with the other K buffer

        if (t < NCH - 1) {
            const int ntn = nbase + (t + 1) * 128;
            const uint32_t kdst = kbb + ((t + 1) & 1) * KBUF;
#pragma unroll
            for (int i = 0; i < 8; i++) {
                int idx = i * 256 + tid;
                int row = idx >> 4, seg = idx & 15;
                cpasync16(kdst + row * 272 + seg * 16,
                          g_kh + (size_t)(ntn + row) * DIM + seg * 8);
            }
            CP_COMMIT();
        }

        const uint32_t kcur = kbb + (t & 1) * KBUF;
        const int n0 = nbase + t * 128;

        float c[2][8][4];
#pragma unroll
        for (int mi = 0; mi < 2; mi++)
#pragma unroll
            for (int nj = 0; nj < 8; nj++)
#pragma unroll
                for (int e = 0; e < 4; e++) c[mi][nj][e] = 0.f;

#pragma unroll
        for (int k16 = 0; k16 < 8; k16++) {
            const int kc = k16 * 16 + acol;
            uint32_t a[2][4], b[4][4];
#pragma unroll
            for (int mi = 0; mi < 2; mi++)
                ldsm4(a[mi], qb + ((wm + mi * 16 + arow) * STRQ + kc) * 2);
#pragma unroll
            for (int nj = 0; nj < 4; nj++)
                ldsm4(b[nj], kcur + ((wn + nj * 16 + arow) * STRQ + kc) * 2);
#pragma unroll
            for (int mi = 0; mi < 2; mi++)
#pragma unroll
                for (int nj = 0; nj < 4; nj++) {
                    mma16816(c[mi][2 * nj], a[mi], b[nj][0], b[nj][2]);
                    mma16816(c[mi][2 * nj + 1], a[mi], b[nj][1], b[nj][3]);
                }
        }

        // exp, accumulate row sums, store e fp16
#pragma unroll
        for (int mi = 0; mi < 2; mi++) {
            float v0 = 0.f, v1 = 0.f;
#pragma unroll
            for (int nj = 0; nj < 8; nj++) {
                c[mi][nj][0] = __expf(c[mi][nj][0]);
                c[mi][nj][1] = __expf(c[mi][nj][1]);
                c[mi][nj][2] = __expf(c[mi][nj][2]);
                c[mi][nj][3] = __expf(c[mi][nj][3]);
                v0 += c[mi][nj][0] + c[mi][nj][1];
                v1 += c[mi][nj][2] + c[mi][nj][3];
                size_t row = (size_t)(m0 + wm + mi * 16 + r0);
                size_t col = (size_t)(n0 + wn + nj * 8 + c0);
                *(uint32_t*)(g_ef16 + row * LK + col) =
                    h2u(__floats2half2_rn(c[mi][nj][0], c[mi][nj][1]));
                *(uint32_t*)(g_ef16 + (row + 8) * LK + col) =
                    h2u(__floats2half2_rn(c[mi][nj][2], c[mi][nj][3]));
            }
            sacc[mi][0] += v0;
            sacc[mi][1] += v1;
        }
    }

    // reduce row sums: shuffle within quads, combine warp halves via smem
    __syncthreads();
    float* rs = (float*)smem;  // [128][2]
#pragma unroll
    for (int mi = 0; mi < 2; mi++) {
        float v0 = sacc[mi][0], v1 = sacc[mi][1];
        v0 += __shfl_xor_sync(0xffffffffu, v0, 1);
        v0 += __shfl_xor_sync(0xffffffffu, v0, 2);
        v1 += __shfl_xor_sync(0xffffffffu, v1, 1);
        v1 += __shfl_xor_sync(0xffffffffu, v1, 2);
        if ((lane & 3) == 0) {
            int r = wm + mi * 16 + (lane >> 2);
            rs[r * 2 + (wid & 1)] = v0;
            rs[(r + 8) * 2 + (wid & 1)] = v1;
        }
    }
    __syncthreads();
    if (tid < 128) {
        g_lpart[(size_t)(m0 + tid) * NCH + blockIdx.x] = rs[tid * 2] + rs[tid * 2 + 1];
    }
}

// ---------------------------------------------------------------------------
// Kernel B: l = sum of NCH partials (fixed order), store 1/l.
// ---------------------------------------------------------------------------
__global__ __launch_bounds__(256) void lred_kernel() {
    const int row = blockIdx.x * 256 + threadIdx.x;
    const float4* p = (const float4*)(g_lpart + (size_t)row * NCH);
    float4 a = p[0], b = p[1];
    g_il[row] = 1.0f / (a.x + a.y + a.z + a.w + b.x + b.y + b.z + b.w);
}

// ---------------------------------------------------------------------------
// Kernel C: streams fp16 e + V through 3-deep cp.async rings.
//   a) att = fp16(e) * il written as fp32 (disjoint tid-partition, float4)
//   b) O_unnorm += e @ V via direct ldsm of the fp16 e tiles
// CTA 512 threads, 128q x 128d; 16 warps in 8q x 2d grid. (R15 champion.)
// ---------------------------------------------------------------------------
__global__ __launch_bounds__(512, 1) void pv_hmma_kernel(float* __restrict__ att) {
    extern __shared__ __align__(16) char smem[];
    const uint32_t pb = smem_u32(smem);                 // e: 3 x [128][STRP] fp16
    __half* Ps = (__half*)smem;
    const uint32_t vbb = pb + 3 * 128 * STRP * 2;       // V: 3 x [128][STRP] fp16
    float* ilrow = (float*)(smem + 6 * 128 * STRP * 2); // [128]
    const int BUF = 128 * STRP * 2;

    const int tid = threadIdx.x, lane = tid & 31, wid = tid >> 5;
    const int q0 = blockIdx.y * 128;
    const int kcnk = blockIdx.x;
    const int kbase = kcnk * (LK / KCH);

    const int qg = (wid & 7) * 16;
    const int dh = (wid >> 3) * 64;
    const int r0 = lane >> 2, c0 = (lane & 3) * 2;
    const int arow = lane & 15, acol = (lane >> 4) * 8;

    if (tid < 128) ilrow[tid] = g_il[q0 + tid];

#pragma unroll
    for (int st = 0; st < 2; st++) {
        const int kb = kbase + st * 64;
#pragma unroll
        for (int i = 0; i < 2; i++) {
            int idx = i * 512 + tid;
            int row = idx >> 3, seg = idx & 7;
            cpasync16(pb + st * BUF + row * (STRP * 2) + seg * 16,
                      g_ef16 + (size_t)(q0 + row) * LK + kb + seg * 8);
        }
#pragma unroll
        for (int i = 0; i < 2; i++) {
            int idx = i * 512 + tid;
            int row = idx >> 3, seg = idx & 7;
            cpasync16(vbb + st * BUF + row * (STRP * 2) + seg * 16,
                      g_vth + (size_t)row * LK + kb + seg * 8);
        }
        CP_COMMIT();
    }

    float o[8][4];
#pragma unroll
    for (int nj = 0; nj < 8; nj++)
#pragma unroll
        for (int e = 0; e < 4; e++) o[nj][e] = 0.f;

    for (int t = 0; t < 16; t++) {
        CP_WAIT(1);
        __syncthreads();

        if (t < 14) {
            const int slot = (t + 2) % 3;
            const int kbn = kbase + (t + 2) * 64;
#pragma unroll
            for (int i = 0; i < 2; i++) {
                int idx = i * 512 + tid;
                int row = idx >> 3, seg = idx & 7;
                cpasync16(pb + slot * BUF + row * (STRP * 2) + seg * 16,
                          g_ef16 + (size_t)(q0 + row) * LK + kbn + seg * 8);
            }
#pragma unroll
            for (int i = 0; i < 2; i++) {
                int idx = i * 512 + tid;
                int row = idx >> 3, seg = idx & 7;
                cpasync16(vbb + slot * BUF + row * (STRP * 2) + seg * 16,
                          g_vth + (size_t)row * LK + kbn + seg * 8);
            }
        }
        CP_COMMIT();

        const int kb = kbase + t * 64;
        const __half* Pc = Ps + (t % 3) * 128 * STRP;
        const uint32_t pcur = pb + (t % 3) * BUF;
        const uint32_t vcur = vbb + (t % 3) * BUF;

#pragma unroll
        for (int i = 0; i < 4; i++) {
            int idx = i * 512 + tid;
            int row = idx >> 4, col4 = (idx & 15) * 4;
            const __half2* hp = (const __half2*)(Pc + row * STRP + col4);
            __half2 e01 = hp[0], e23 = hp[1];
            const float il = ilrow[row];
            float4 s;
            s.x = __low2float(e01) * il;
            s.y = __high2float(e01) * il;
            s.z = __low2float(e23) * il;
            s.w = __high2float(e23) * il;
            *(float4*)(att + (size_t)(q0 + row) * LK + kb + col4) = s;
        }

#pragma unroll
        for (int k16 = 0; k16 < 4; k16++) {
            const int kc = k16 * 16 + acol;
            uint32_t ah[4];
            ldsm4(ah, pcur + ((qg + arow) * STRP + kc) * 2);
#pragma unroll
            for (int nj = 0; nj < 4; nj++) {
                uint32_t bv[4];
                ldsm4(bv, vcur + ((dh + nj * 16 + arow) * STRP + kc) * 2);
                mma16816(o[2 * nj], ah, bv[0], bv[2]);
                mma16816(o[2 * nj + 1], ah, bv[1], bv[3]);
            }
        }
    }

    float* op = g_opart + (size_t)kcnk * ((size_t)LQ * DIM);
#pragma unroll
    for (int n8 = 0; n8 < 8; n8++) {
        size_t row = (size_t)(q0 + qg + r0);
        size_t col = (size_t)(dh + n8 * 8 + c0);
        *(float2*)(op + row * DIM + col) = make_float2(o[n8][0], o[n8][1]);
        *(float2*)(op + (row + 8) * DIM + col) = make_float2(o[n8][2], o[n8][3]);
    }
}

// ---------------------------------------------------------------------------
// Kernel D: reduce KCH partials into out, applying il[row] once.
// ---------------------------------------------------------------------------
__global__ __launch_bounds__(256) void reduce_kernel(float* __restrict__ out) {
    const size_t i = (size_t)blockIdx.x * 256 + threadIdx.x;
    float s = 0.f;
#pragma unroll
    for (int c = 0; c < KCH; c++) s += g_opart[(size_t)c * LQ * DIM + i];
    out[i] = s * g_il[i >> 7];
}

// ---------------------------------------------------------------------------
extern "C" void kernel_launch(void* const* d_in, const int* in_sizes, int n_in,
                              void* d_out, int out_size) {
    const float* Q = (const float*)d_in[0];
    const float* K = (const float*)d_in[1];
    const float* V = (const float*)d_in[2];
    float* out = (float*)d_out;             // [LQ, DIM]
    float* att = out + (size_t)LQ * DIM;    // [LQ, LK]

    const int smemA = 3 * 128 * STRQ * 2;           // 104448
    const int smemC = 6 * 128 * STRP * 2 + 512;     // 111104
    cudaFuncSetAttribute(qk_hmma_kernel, cudaFuncAttributeMaxDynamicSharedMemorySize, smemA);
    cudaFuncSetAttribute(pv_hmma_kernel, cudaFuncAttributeMaxDynamicSharedMemorySize, smemC);

    prep_kernel<<<(LQ * DIM) / 256, 256>>>(Q, K, V);
    qk_hmma_kernel<<<dim3(NCH, LQ / 128), 256, smemA>>>();
    lred_kernel<<<LQ / 256, 256>>>();
    pv_hmma_kernel<<<dim3(KCH, LQ / 128), 512, smemC>>>(att);
    reduce_kernel<<<(LQ * DIM) / 256, 256>>>(out);
}